// round 7
// baseline (speedup 1.0000x reference)
#include <cuda_runtime.h>
#include <stdint.h>

#define D        128
#define LDS_     132     // padded SMEM row stride (floats): conflict-free A-frag loads
#define MT       128     // rows per CTA
#define NTHREADS 512     // 16 warps: 8 (M) x 2 (N)

// ---------------------------------------------------------------------------
// Bias precompute: b = column sums of the 128x128 "bias" matrices
// ---------------------------------------------------------------------------
__device__ float g_bias[3 * D];   // [0:128)=b_z  [128:256)=b_r  [256:384)=b_h

__global__ void bias_kernel(const float* __restrict__ Bz,
                            const float* __restrict__ Br,
                            const float* __restrict__ Bh) {
    int j = threadIdx.x;            // 0..127
    float sz = 0.f, sr = 0.f, sh = 0.f;
    for (int i = 0; i < D; ++i) {
        sz += Bz[i * D + j];
        sr += Br[i * D + j];
        sh += Bh[i * D + j];
    }
    g_bias[j]         = sz;
    g_bias[D + j]     = sr;
    g_bias[2 * D + j] = sh;
}

// ---------------------------------------------------------------------------
// TF32 helpers
// ---------------------------------------------------------------------------
__device__ __forceinline__ uint32_t f2t(float f) {
    uint32_t u;
    asm("cvt.rna.tf32.f32 %0, %1;" : "=r"(u) : "f"(f));
    return u;
}

__device__ __forceinline__ void mma8(float* d, const uint32_t* a, uint32_t b0, uint32_t b1) {
    asm volatile(
        "mma.sync.aligned.m16n8k8.row.col.f32.tf32.tf32.f32 "
        "{%0,%1,%2,%3}, {%4,%5,%6,%7}, {%8,%9}, {%0,%1,%2,%3};"
        : "+f"(d[0]), "+f"(d[1]), "+f"(d[2]), "+f"(d[3])
        : "r"(a[0]), "r"(a[1]), "r"(a[2]), "r"(a[3]), "r"(b0), "r"(b1));
}

__device__ __forceinline__ float sigmoidf_(float v) {
    return 1.0f / (1.0f + expf(-v));
}

// ---------------------------------------------------------------------------
// SMEM staging: 128x128 fp32 gmem tile -> padded SMEM (stride 132)
// ---------------------------------------------------------------------------
__device__ __forceinline__ void stage128(const float* __restrict__ gsrc, float* __restrict__ s) {
#pragma unroll
    for (int i = 0; i < 8; ++i) {
        int idx = threadIdx.x + i * NTHREADS;  // 4096 float4 tiles
        int r = idx >> 5;                      // row 0..127
        int c = (idx & 31) << 2;               // col 0..124 step 4
        float4 v = *(const float4*)(gsrc + r * D + c);
        *(float4*)(s + r * LDS_ + c) = v;
    }
}

__device__ __forceinline__ void stage128_sum(const float* __restrict__ ga,
                                             const float* __restrict__ gb,
                                             float* __restrict__ s) {
#pragma unroll
    for (int i = 0; i < 8; ++i) {
        int idx = threadIdx.x + i * NTHREADS;
        int r = idx >> 5;
        int c = (idx & 31) << 2;
        float4 va = *(const float4*)(ga + r * D + c);
        float4 vb = *(const float4*)(gb + r * D + c);
        float4 v = make_float4(va.x + vb.x, va.y + vb.y, va.z + vb.z, va.w + vb.w);
        *(float4*)(s + r * LDS_ + c) = v;
    }
}

// ---------------------------------------------------------------------------
// One warp-tile GEMM slab: 16(M) x 64(N) x 128(K), accumulate into acc[8][4].
// TR=false: Bs laid out [k][n] (B(k,n) = W[k,n], computes A @ W)
// TR=true : Bs laid out [n][k] (B(k,n) = W[n,k], computes A @ W^T)
// ---------------------------------------------------------------------------
template <bool TR>
__device__ __forceinline__ void gemm_tile(const float* __restrict__ As,
                                          const float* __restrict__ Bs,
                                          float acc[8][4],
                                          int mrow0, int ncol0, int g, int t) {
    const float* a0p = As + (mrow0 + g)     * LDS_;
    const float* a1p = As + (mrow0 + g + 8) * LDS_;
#pragma unroll
    for (int kk = 0; kk < 16; ++kk) {
        const int k0 = kk * 8;
        uint32_t a[4];
        a[0] = f2t(a0p[k0 + t]);
        a[1] = f2t(a1p[k0 + t]);
        a[2] = f2t(a0p[k0 + t + 4]);
        a[3] = f2t(a1p[k0 + t + 4]);
#pragma unroll
        for (int nc = 0; nc < 8; ++nc) {
            const int n = ncol0 + nc * 8 + g;
            uint32_t b0, b1;
            if (TR) {
                b0 = f2t(Bs[n * LDS_ + k0 + t]);
                b1 = f2t(Bs[n * LDS_ + k0 + t + 4]);
            } else {
                b0 = f2t(Bs[(k0 + t) * LDS_ + n]);
                b1 = f2t(Bs[(k0 + t + 4) * LDS_ + n]);
            }
            mma8(acc[nc], a, b0, b1);
        }
    }
}

// ---------------------------------------------------------------------------
// Fused GRU kernel: one CTA handles 128 rows end-to-end.
// ---------------------------------------------------------------------------
__global__ __launch_bounds__(NTHREADS, 1)
void gru_kernel(const float* __restrict__ x, const float* __restrict__ h,
                const float* __restrict__ Wz, const float* __restrict__ Uz,
                const float* __restrict__ Wr, const float* __restrict__ Ur,
                const float* __restrict__ Wh, const float* __restrict__ Uh,
                float* __restrict__ out, long long half_off) {
    extern __shared__ float sm[];
    float* xs = sm;                     // [128][132] x tile
    float* hs = sm + MT * LDS_;        // [128][132] h tile (later: r*h)
    float* ws = sm + 2 * MT * LDS_;    // [128][132] weight panel

    const int tid   = threadIdx.x;
    const int lane  = tid & 31;
    const int warp  = tid >> 5;
    const int g     = lane >> 2;         // group id 0..7
    const int t     = lane & 3;          // thread-in-group 0..3
    const int mrow0 = (warp >> 1) * 16;  // 0..112
    const int ncol0 = (warp & 1) * 64;   // 0 or 64
    const long long row0 = (long long)blockIdx.x * MT;

    // ---- stage x, h, and W_update ----
    stage128(x + row0 * D, xs);
    stage128(h + row0 * D, hs);
    stage128(Wz, ws);
    __syncthreads();

    // ---- z_pre = x@Wz + h@Uz ----
    float accZ[8][4];
#pragma unroll
    for (int nc = 0; nc < 8; ++nc)
#pragma unroll
        for (int j = 0; j < 4; ++j) accZ[nc][j] = 0.f;

    gemm_tile<false>(xs, ws, accZ, mrow0, ncol0, g, t);
    __syncthreads();
    stage128(Uz, ws);
    __syncthreads();
    gemm_tile<false>(hs, ws, accZ, mrow0, ncol0, g, t);

    // ---- z = sigmoid(z_pre + b_z), kept in registers ----
    float z[8][4];
#pragma unroll
    for (int nc = 0; nc < 8; ++nc) {
        int c0 = ncol0 + nc * 8 + 2 * t;
        float b0 = g_bias[c0], b1 = g_bias[c0 + 1];
        z[nc][0] = sigmoidf_(accZ[nc][0] + b0);
        z[nc][1] = sigmoidf_(accZ[nc][1] + b1);
        z[nc][2] = sigmoidf_(accZ[nc][2] + b0);
        z[nc][3] = sigmoidf_(accZ[nc][3] + b1);
    }

    // ---- r_pre = x@(Wr+Ur)  (reference uses x for both reset terms) ----
    __syncthreads();
    stage128_sum(Wr, Ur, ws);
    __syncthreads();

    float acc[8][4];
#pragma unroll
    for (int nc = 0; nc < 8; ++nc)
#pragma unroll
        for (int j = 0; j < 4; ++j) acc[nc][j] = 0.f;
    gemm_tile<false>(xs, ws, acc, mrow0, ncol0, g, t);

    // ---- r = sigmoid(r_pre + b_r); capture h; write rh into hs ----
    float hk[8][4];
#pragma unroll
    for (int nc = 0; nc < 8; ++nc) {
        int c0 = ncol0 + nc * 8 + 2 * t;
        float b0 = g_bias[D + c0], b1 = g_bias[D + c0 + 1];
        int rA = mrow0 + g, rB = rA + 8;
        float2 hA = *(float2*)(hs + rA * LDS_ + c0);
        float2 hB = *(float2*)(hs + rB * LDS_ + c0);
        float r0 = sigmoidf_(acc[nc][0] + b0);
        float r1 = sigmoidf_(acc[nc][1] + b1);
        float r2 = sigmoidf_(acc[nc][2] + b0);
        float r3 = sigmoidf_(acc[nc][3] + b1);
        hk[nc][0] = hA.x; hk[nc][1] = hA.y; hk[nc][2] = hB.x; hk[nc][3] = hB.y;
        *(float2*)(hs + rA * LDS_ + c0) = make_float2(r0 * hA.x, r1 * hA.y);
        *(float2*)(hs + rB * LDS_ + c0) = make_float2(r2 * hB.x, r3 * hB.y);
    }

    // ---- hc_pre = x@Wh^T + rh@Uh^T ----
    __syncthreads();
    stage128(Wh, ws);          // row-major copy == [n][k] layout for B
    __syncthreads();
#pragma unroll
    for (int nc = 0; nc < 8; ++nc)
#pragma unroll
        for (int j = 0; j < 4; ++j) acc[nc][j] = 0.f;
    gemm_tile<true>(xs, ws, acc, mrow0, ncol0, g, t);
    __syncthreads();
    stage128(Uh, ws);
    __syncthreads();
    gemm_tile<true>(hs, ws, acc, mrow0, ncol0, g, t);   // hs now holds r*h

    // ---- epilogue: h_cand = tanh(hc_pre + b_h); h_t = (1-z)h + z*h_cand ----
#pragma unroll
    for (int nc = 0; nc < 8; ++nc) {
        int c0 = ncol0 + nc * 8 + 2 * t;
        float b0 = g_bias[2 * D + c0], b1 = g_bias[2 * D + c0 + 1];
        long long rA = row0 + mrow0 + g;
        long long rB = rA + 8;
        float hc0 = tanhf(acc[nc][0] + b0);
        float hc1 = tanhf(acc[nc][1] + b1);
        float hc2 = tanhf(acc[nc][2] + b0);
        float hc3 = tanhf(acc[nc][3] + b1);
        float ht0 = (1.f - z[nc][0]) * hk[nc][0] + z[nc][0] * hc0;
        float ht1 = (1.f - z[nc][1]) * hk[nc][1] + z[nc][1] * hc1;
        float ht2 = (1.f - z[nc][2]) * hk[nc][2] + z[nc][2] * hc2;
        float ht3 = (1.f - z[nc][3]) * hk[nc][3] + z[nc][3] * hc3;
        *(float2*)(out + rA * D + c0)            = make_float2(ht0, ht1);
        *(float2*)(out + rB * D + c0)            = make_float2(ht2, ht3);
        *(float2*)(out + half_off + rA * D + c0) = make_float2(hc0, hc1);
        *(float2*)(out + half_off + rB * D + c0) = make_float2(hc2, hc3);
    }
}

// ---------------------------------------------------------------------------
// Launch
// ---------------------------------------------------------------------------
extern "C" void kernel_launch(void* const* d_in, const int* in_sizes, int n_in,
                              void* d_out, int out_size) {
    const float* x  = (const float*)d_in[0];
    const float* h  = (const float*)d_in[1];
    const float* Wz = (const float*)d_in[2];
    const float* Uz = (const float*)d_in[3];
    const float* Bz = (const float*)d_in[4];
    const float* Wr = (const float*)d_in[5];
    const float* Ur = (const float*)d_in[6];
    const float* Br = (const float*)d_in[7];
    const float* Wh = (const float*)d_in[8];
    const float* Uh = (const float*)d_in[9];
    const float* Bh = (const float*)d_in[10];

    const int rows = in_sizes[0] / D;          // 262144
    const int grid = rows / MT;                // 2048 CTAs
    const size_t smem = (size_t)3 * MT * LDS_ * sizeof(float);  // 202752 B

    cudaFuncSetAttribute(gru_kernel, cudaFuncAttributeMaxDynamicSharedMemorySize, (int)smem);

    bias_kernel<<<1, D>>>(Bz, Br, Bh);

    long long half_off = (long long)out_size / 2;   // h_t first, h_cand second
    gru_kernel<<<grid, NTHREADS, smem>>>(x, h, Wz, Uz, Wr, Ur, Wh, Uh,
                                         (float*)d_out, half_off);
}

// round 8
// speedup vs baseline: 1.0061x; 1.0061x over previous
#include <cuda_runtime.h>
#include <stdint.h>

#define D        128
#define LDS_     132     // padded SMEM row stride (floats): conflict-free A-frag loads
#define MT       128     // rows per CTA
#define NTHREADS 512     // 16 warps: 8 (M) x 2 (N)

// ---------------------------------------------------------------------------
// Bias precompute: b = column sums of the 128x128 "bias" matrices
// ---------------------------------------------------------------------------
__device__ float g_bias[3 * D];   // [0:128)=b_z  [128:256)=b_r  [256:384)=b_h

__global__ void bias_kernel(const float* __restrict__ Bz,
                            const float* __restrict__ Br,
                            const float* __restrict__ Bh) {
    int j = threadIdx.x;            // 0..127
    float sz = 0.f, sr = 0.f, sh = 0.f;
    for (int i = 0; i < D; ++i) {
        sz += Bz[i * D + j];
        sr += Br[i * D + j];
        sh += Bh[i * D + j];
    }
    g_bias[j]         = sz;
    g_bias[D + j]     = sr;
    g_bias[2 * D + j] = sh;
}

// ---------------------------------------------------------------------------
// TF32 helpers
// ---------------------------------------------------------------------------
__device__ __forceinline__ uint32_t f2t(float f) {
    uint32_t u;
    asm("cvt.rna.tf32.f32 %0, %1;" : "=r"(u) : "f"(f));
    return u;
}

__device__ __forceinline__ void mma8(float* d, const uint32_t* a, uint32_t b0, uint32_t b1) {
    asm volatile(
        "mma.sync.aligned.m16n8k8.row.col.f32.tf32.tf32.f32 "
        "{%0,%1,%2,%3}, {%4,%5,%6,%7}, {%8,%9}, {%0,%1,%2,%3};"
        : "+f"(d[0]), "+f"(d[1]), "+f"(d[2]), "+f"(d[3])
        : "r"(a[0]), "r"(a[1]), "r"(a[2]), "r"(a[3]), "r"(b0), "r"(b1));
}

__device__ __forceinline__ float sigmoidf_(float v) {
    return 1.0f / (1.0f + expf(-v));
}

// ---------------------------------------------------------------------------
// SMEM staging: 128x128 fp32 gmem tile -> padded SMEM (stride 132)
// ---------------------------------------------------------------------------
__device__ __forceinline__ void stage128(const float* __restrict__ gsrc, float* __restrict__ s) {
#pragma unroll
    for (int i = 0; i < 8; ++i) {
        int idx = threadIdx.x + i * NTHREADS;  // 4096 float4 tiles
        int r = idx >> 5;                      // row 0..127
        int c = (idx & 31) << 2;               // col 0..124 step 4
        float4 v = *(const float4*)(gsrc + r * D + c);
        *(float4*)(s + r * LDS_ + c) = v;
    }
}

__device__ __forceinline__ void stage128_sum(const float* __restrict__ ga,
                                             const float* __restrict__ gb,
                                             float* __restrict__ s) {
#pragma unroll
    for (int i = 0; i < 8; ++i) {
        int idx = threadIdx.x + i * NTHREADS;
        int r = idx >> 5;
        int c = (idx & 31) << 2;
        float4 va = *(const float4*)(ga + r * D + c);
        float4 vb = *(const float4*)(gb + r * D + c);
        float4 v = make_float4(va.x + vb.x, va.y + vb.y, va.z + vb.z, va.w + vb.w);
        *(float4*)(s + r * LDS_ + c) = v;
    }
}

// ---------------------------------------------------------------------------
// One warp-tile GEMM slab: 16(M) x 64(N) x 128(K), accumulate into acc[8][4].
// TR=false: Bs laid out [k][n] (B(k,n) = W[k,n], computes A @ W)
// TR=true : Bs laid out [n][k] (B(k,n) = W[n,k], computes A @ W^T)
// ---------------------------------------------------------------------------
template <bool TR>
__device__ __forceinline__ void gemm_tile(const float* __restrict__ As,
                                          const float* __restrict__ Bs,
                                          float acc[8][4],
                                          int mrow0, int ncol0, int g, int t) {
    const float* a0p = As + (mrow0 + g)     * LDS_;
    const float* a1p = As + (mrow0 + g + 8) * LDS_;
#pragma unroll
    for (int kk = 0; kk < 16; ++kk) {
        const int k0 = kk * 8;
        uint32_t a[4];
        a[0] = f2t(a0p[k0 + t]);
        a[1] = f2t(a1p[k0 + t]);
        a[2] = f2t(a0p[k0 + t + 4]);
        a[3] = f2t(a1p[k0 + t + 4]);
#pragma unroll
        for (int nc = 0; nc < 8; ++nc) {
            const int n = ncol0 + nc * 8 + g;
            uint32_t b0, b1;
            if (TR) {
                b0 = f2t(Bs[n * LDS_ + k0 + t]);
                b1 = f2t(Bs[n * LDS_ + k0 + t + 4]);
            } else {
                b0 = f2t(Bs[(k0 + t) * LDS_ + n]);
                b1 = f2t(Bs[(k0 + t + 4) * LDS_ + n]);
            }
            mma8(acc[nc], a, b0, b1);
        }
    }
}

// ---------------------------------------------------------------------------
// Fused GRU kernel: one CTA handles 128 rows end-to-end.
// ---------------------------------------------------------------------------
__global__ __launch_bounds__(NTHREADS, 1)
void gru_kernel(const float* __restrict__ x, const float* __restrict__ h,
                const float* __restrict__ Wz, const float* __restrict__ Uz,
                const float* __restrict__ Wr, const float* __restrict__ Ur,
                const float* __restrict__ Wh, const float* __restrict__ Uh,
                float* __restrict__ out, long long half_off) {
    extern __shared__ float sm[];
    float* xs = sm;                     // [128][132] x tile
    float* hs = sm + MT * LDS_;        // [128][132] h tile (later: r*h)
    float* ws = sm + 2 * MT * LDS_;    // [128][132] weight panel

    const int tid   = threadIdx.x;
    const int lane  = tid & 31;
    const int warp  = tid >> 5;
    const int g     = lane >> 2;         // group id 0..7
    const int t     = lane & 3;          // thread-in-group 0..3
    const int mrow0 = (warp >> 1) * 16;  // 0..112
    const int ncol0 = (warp & 1) * 64;   // 0 or 64
    const long long row0 = (long long)blockIdx.x * MT;

    // ---- stage x, h, and W_update ----
    stage128(x + row0 * D, xs);
    stage128(h + row0 * D, hs);
    stage128(Wz, ws);
    __syncthreads();

    // ---- z_pre = x@Wz + h@Uz ----
    float accZ[8][4];
#pragma unroll
    for (int nc = 0; nc < 8; ++nc)
#pragma unroll
        for (int j = 0; j < 4; ++j) accZ[nc][j] = 0.f;

    gemm_tile<false>(xs, ws, accZ, mrow0, ncol0, g, t);
    __syncthreads();
    stage128(Uz, ws);
    __syncthreads();
    gemm_tile<false>(hs, ws, accZ, mrow0, ncol0, g, t);

    // ---- z = sigmoid(z_pre + b_z), kept in registers ----
    float z[8][4];
#pragma unroll
    for (int nc = 0; nc < 8; ++nc) {
        int c0 = ncol0 + nc * 8 + 2 * t;
        float b0 = g_bias[c0], b1 = g_bias[c0 + 1];
        z[nc][0] = sigmoidf_(accZ[nc][0] + b0);
        z[nc][1] = sigmoidf_(accZ[nc][1] + b1);
        z[nc][2] = sigmoidf_(accZ[nc][2] + b0);
        z[nc][3] = sigmoidf_(accZ[nc][3] + b1);
    }

    // ---- r_pre = x@(Wr+Ur)  (reference uses x for both reset terms) ----
    __syncthreads();
    stage128_sum(Wr, Ur, ws);
    __syncthreads();

    float acc[8][4];
#pragma unroll
    for (int nc = 0; nc < 8; ++nc)
#pragma unroll
        for (int j = 0; j < 4; ++j) acc[nc][j] = 0.f;
    gemm_tile<false>(xs, ws, acc, mrow0, ncol0, g, t);

    // ---- r = sigmoid(r_pre + b_r); capture h; write rh into hs ----
    float hk[8][4];
#pragma unroll
    for (int nc = 0; nc < 8; ++nc) {
        int c0 = ncol0 + nc * 8 + 2 * t;
        float b0 = g_bias[D + c0], b1 = g_bias[D + c0 + 1];
        int rA = mrow0 + g, rB = rA + 8;
        float2 hA = *(float2*)(hs + rA * LDS_ + c0);
        float2 hB = *(float2*)(hs + rB * LDS_ + c0);
        float r0 = sigmoidf_(acc[nc][0] + b0);
        float r1 = sigmoidf_(acc[nc][1] + b1);
        float r2 = sigmoidf_(acc[nc][2] + b0);
        float r3 = sigmoidf_(acc[nc][3] + b1);
        hk[nc][0] = hA.x; hk[nc][1] = hA.y; hk[nc][2] = hB.x; hk[nc][3] = hB.y;
        *(float2*)(hs + rA * LDS_ + c0) = make_float2(r0 * hA.x, r1 * hA.y);
        *(float2*)(hs + rB * LDS_ + c0) = make_float2(r2 * hB.x, r3 * hB.y);
    }

    // ---- hc_pre = x@Wh^T + rh@Uh^T ----
    __syncthreads();
    stage128(Wh, ws);          // row-major copy == [n][k] layout for B
    __syncthreads();
#pragma unroll
    for (int nc = 0; nc < 8; ++nc)
#pragma unroll
        for (int j = 0; j < 4; ++j) acc[nc][j] = 0.f;
    gemm_tile<true>(xs, ws, acc, mrow0, ncol0, g, t);
    __syncthreads();
    stage128(Uh, ws);
    __syncthreads();
    gemm_tile<true>(hs, ws, acc, mrow0, ncol0, g, t);   // hs now holds r*h

    // ---- epilogue: h_cand = tanh(hc_pre + b_h); h_t = (1-z)h + z*h_cand ----
#pragma unroll
    for (int nc = 0; nc < 8; ++nc) {
        int c0 = ncol0 + nc * 8 + 2 * t;
        float b0 = g_bias[2 * D + c0], b1 = g_bias[2 * D + c0 + 1];
        long long rA = row0 + mrow0 + g;
        long long rB = rA + 8;
        float hc0 = tanhf(acc[nc][0] + b0);
        float hc1 = tanhf(acc[nc][1] + b1);
        float hc2 = tanhf(acc[nc][2] + b0);
        float hc3 = tanhf(acc[nc][3] + b1);
        float ht0 = (1.f - z[nc][0]) * hk[nc][0] + z[nc][0] * hc0;
        float ht1 = (1.f - z[nc][1]) * hk[nc][1] + z[nc][1] * hc1;
        float ht2 = (1.f - z[nc][2]) * hk[nc][2] + z[nc][2] * hc2;
        float ht3 = (1.f - z[nc][3]) * hk[nc][3] + z[nc][3] * hc3;
        *(float2*)(out + rA * D + c0)            = make_float2(ht0, ht1);
        *(float2*)(out + rB * D + c0)            = make_float2(ht2, ht3);
        *(float2*)(out + half_off + rA * D + c0) = make_float2(hc0, hc1);
        *(float2*)(out + half_off + rB * D + c0) = make_float2(hc2, hc3);
    }
}

// ---------------------------------------------------------------------------
// Launch
// ---------------------------------------------------------------------------
extern "C" void kernel_launch(void* const* d_in, const int* in_sizes, int n_in,
                              void* d_out, int out_size) {
    const float* x  = (const float*)d_in[0];
    const float* h  = (const float*)d_in[1];
    const float* Wz = (const float*)d_in[2];
    const float* Uz = (const float*)d_in[3];
    const float* Bz = (const float*)d_in[4];
    const float* Wr = (const float*)d_in[5];
    const float* Ur = (const float*)d_in[6];
    const float* Br = (const float*)d_in[7];
    const float* Wh = (const float*)d_in[8];
    const float* Uh = (const float*)d_in[9];
    const float* Bh = (const float*)d_in[10];

    const int rows = in_sizes[0] / D;          // 262144
    const int grid = rows / MT;                // 2048 CTAs
    const size_t smem = (size_t)3 * MT * LDS_ * sizeof(float);  // 202752 B

    cudaFuncSetAttribute(gru_kernel, cudaFuncAttributeMaxDynamicSharedMemorySize, (int)smem);

    bias_kernel<<<1, D>>>(Bz, Br, Bh);

    long long half_off = (long long)out_size / 2;   // h_t first, h_cand second
    gru_kernel<<<grid, NTHREADS, smem>>>(x, h, Wz, Uz, Wr, Ur, Wh, Uh,
                                         (float*)d_out, half_off);
}

// round 11
// speedup vs baseline: 1.1051x; 1.0983x over previous
#include <cuda_runtime.h>
#include <stdint.h>

#define D   128
#define NT  512
#define LDA 132                 // activation SMEM stride (floats): bank 4r+c, conflict-free frags
#define LDB 68                  // weight half-panel stride: bank = 4n+k -> B frags conflict-free

// SMEM float offsets
#define XS    0                 // x tile [128][132], tf32-rounded
#define HS    (128 * LDA)       // h tile [128][132] exact; later holds rounded r*h
#define W0    (2 * 128 * LDA)   // weight half-panel 0 [128n][68]
#define W1    (W0 + 128 * LDB)  // weight half-panel 1
#define SBIAS (W1 + 128 * LDB)  // 384 bias floats
#define SMEM_BYTES ((SBIAS + 384) * 4)

// ---------------------------------------------------------------------------
// bias precompute: column sums of the three 128x128 "bias" matrices
// ---------------------------------------------------------------------------
__device__ float g_bias[3 * D];

__global__ void bias_kernel(const float* __restrict__ Bz,
                            const float* __restrict__ Br,
                            const float* __restrict__ Bh) {
    int j = threadIdx.x;
    float sz = 0.f, sr = 0.f, sh = 0.f;
    for (int i = 0; i < D; ++i) {
        sz += Bz[i * D + j];
        sr += Br[i * D + j];
        sh += Bh[i * D + j];
    }
    g_bias[j] = sz; g_bias[D + j] = sr; g_bias[2 * D + j] = sh;
}

// ---------------------------------------------------------------------------
// helpers
// ---------------------------------------------------------------------------
__device__ __forceinline__ float f2tf(float f) {          // round fp32 -> tf32 grid
    uint32_t u;
    asm("cvt.rna.tf32.f32 %0, %1;" : "=r"(u) : "f"(f));
    return __uint_as_float(u);
}
__device__ __forceinline__ uint32_t cvt_t(uint32_t x) {   // round raw fp32 bits -> tf32 bits
    uint32_t u;
    asm("cvt.rna.tf32.f32 %0, %1;" : "=r"(u) : "f"(__uint_as_float(x)));
    return u;
}
__device__ __forceinline__ float sigmoidf_(float v) { return 1.0f / (1.0f + expf(-v)); }

__device__ __forceinline__ void mma8(float* d, const uint32_t* a, uint32_t b0, uint32_t b1) {
    asm volatile(
        "mma.sync.aligned.m16n8k8.row.col.f32.tf32.tf32.f32 "
        "{%0,%1,%2,%3}, {%4,%5,%6,%7}, {%8,%9}, {%0,%1,%2,%3};"
        : "+f"(d[0]), "+f"(d[1]), "+f"(d[2]), "+f"(d[3])
        : "r"(a[0]), "r"(a[1]), "r"(a[2]), "r"(a[3]), "r"(b0), "r"(b1));
}

// ---------------------------------------------------------------------------
// weight half-panel prefetch (gmem -> regs) and store (regs -> SMEM [n][k])
// each thread owns 4 float4s: (n = linear&127, kq = linear>>7), element [n][4kq..4kq+3]
// ---------------------------------------------------------------------------
__device__ __forceinline__ void ldg_nat(const float* __restrict__ w, int half,
                                        float4* pf, int tid) {
#pragma unroll
    for (int i = 0; i < 4; ++i) {
        int linear = tid + i * NT;
        int n = linear & 127, kq = linear >> 7;
        float4 v = *(const float4*)(w + n * D + half * 64 + kq * 4);
        pf[i] = make_float4(f2tf(v.x), f2tf(v.y), f2tf(v.z), f2tf(v.w));
    }
}
__device__ __forceinline__ void ldg_tr(const float* __restrict__ w, int half,
                                       float4* pf, int tid) {
#pragma unroll
    for (int i = 0; i < 4; ++i) {
        int linear = tid + i * NT;
        int n = linear & 127, kq = linear >> 7;
        int gk = half * 64 + kq * 4;
        pf[i] = make_float4(f2tf(w[(gk + 0) * D + n]), f2tf(w[(gk + 1) * D + n]),
                            f2tf(w[(gk + 2) * D + n]), f2tf(w[(gk + 3) * D + n]));
    }
}
__device__ __forceinline__ void ldg_trsum(const float* __restrict__ wa,
                                          const float* __restrict__ wb, int half,
                                          float4* pf, int tid) {
#pragma unroll
    for (int i = 0; i < 4; ++i) {
        int linear = tid + i * NT;
        int n = linear & 127, kq = linear >> 7;
        int gk = half * 64 + kq * 4;
        pf[i] = make_float4(f2tf(wa[(gk + 0) * D + n] + wb[(gk + 0) * D + n]),
                            f2tf(wa[(gk + 1) * D + n] + wb[(gk + 1) * D + n]),
                            f2tf(wa[(gk + 2) * D + n] + wb[(gk + 2) * D + n]),
                            f2tf(wa[(gk + 3) * D + n] + wb[(gk + 3) * D + n]));
    }
}
__device__ __forceinline__ void sts_w(float* __restrict__ buf, const float4* pf, int tid) {
#pragma unroll
    for (int i = 0; i < 4; ++i) {
        int linear = tid + i * NT;
        int n = linear & 127, kq = linear >> 7;
        *(float4*)(buf + n * LDB + kq * 4) = pf[i];
    }
}

// ---------------------------------------------------------------------------
// one K-half GEMM slab: 16M x 64N x 64K per warp.
// As must point at the A tile PLUS the K-half column offset (0 or 64).   <-- R10 bugfix
// A bank 4r+c (conflict-free), B bank 4n+k (conflict-free).
// CVT: round A frags at load (only for exact-fp32 A tiles, i.e. h).
// ---------------------------------------------------------------------------
template <bool CVT>
__device__ __forceinline__ void mma_half(const float* __restrict__ As,
                                         const float* __restrict__ Bs,
                                         float acc[8][4],
                                         int mrow0, int ncol0, int g, int t) {
    const float* a0p = As + (mrow0 + g) * LDA;
    const float* a1p = a0p + 8 * LDA;
#pragma unroll
    for (int kk = 0; kk < 8; ++kk) {
        const int k0 = kk * 8;
        uint32_t a[4];
        a[0] = __float_as_uint(a0p[k0 + t]);
        a[1] = __float_as_uint(a1p[k0 + t]);
        a[2] = __float_as_uint(a0p[k0 + t + 4]);
        a[3] = __float_as_uint(a1p[k0 + t + 4]);
        if (CVT) {
            a[0] = cvt_t(a[0]); a[1] = cvt_t(a[1]);
            a[2] = cvt_t(a[2]); a[3] = cvt_t(a[3]);
        }
#pragma unroll
        for (int nc = 0; nc < 8; ++nc) {
            const int n = ncol0 + nc * 8 + g;
            uint32_t b0 = __float_as_uint(Bs[n * LDB + k0 + t]);
            uint32_t b1 = __float_as_uint(Bs[n * LDB + k0 + t + 4]);
            mma8(acc[nc], a, b0, b1);
        }
    }
}

#define ZERO_ACC(A)                                      \
    _Pragma("unroll") for (int nc = 0; nc < 8; ++nc)     \
    _Pragma("unroll") for (int j = 0; j < 4; ++j) (A)[nc][j] = 0.f

// ---------------------------------------------------------------------------
// fused GRU: one CTA = 128 rows; 10 pipelined half-GEMMs; all-[n][k] weights
// ---------------------------------------------------------------------------
__global__ __launch_bounds__(NT, 1)
void gru_kernel(const float* __restrict__ x, const float* __restrict__ h,
                const float* __restrict__ Wz, const float* __restrict__ Uz,
                const float* __restrict__ Wr, const float* __restrict__ Ur,
                const float* __restrict__ Wh, const float* __restrict__ Uh,
                float* __restrict__ out, long long half_off) {
    extern __shared__ float sm[];
    const int tid   = threadIdx.x;
    const int lane  = tid & 31;
    const int warp  = tid >> 5;
    const int g     = lane >> 2;
    const int t     = lane & 3;
    const int mrow0 = (warp >> 1) * 16;
    const int ncol0 = (warp & 1) * 64;
    const long long row0 = (long long)blockIdx.x * 128;

    // A-tile base pointers per K-half (the R10 bug: half-1 slabs must read cols 64..127)
    const float* xs0 = sm + XS;       const float* xs1 = sm + XS + 64;
    const float* hs0 = sm + HS;       const float* hs1 = sm + HS + 64;

    // ---- stage x (tf32-rounded) and h (exact) ----
#pragma unroll
    for (int i = 0; i < 8; ++i) {
        int idx = tid + i * NT;
        int r = idx >> 5, c = (idx & 31) << 2;
        float4 vx = *(const float4*)(x + (row0 + r) * D + c);
        *(float4*)(sm + XS + r * LDA + c) =
            make_float4(f2tf(vx.x), f2tf(vx.y), f2tf(vx.z), f2tf(vx.w));
        float4 vh = *(const float4*)(h + (row0 + r) * D + c);
        *(float4*)(sm + HS + r * LDA + c) = vh;
    }
    if (tid < 384) sm[SBIAS + tid] = g_bias[tid];

    float4 pf[4];
    ldg_tr(Wz, 0, pf, tid); sts_w(sm + W0, pf, tid);
    __syncthreads();

    float accZ[8][4], acc[8][4];
    ZERO_ACC(accZ);

    // H0: x@Wz (half 0)
    ldg_tr(Wz, 1, pf, tid);
    mma_half<false>(xs0, sm + W0, accZ, mrow0, ncol0, g, t);
    sts_w(sm + W1, pf, tid); __syncthreads();
    // H1: x@Wz (half 1)
    ldg_tr(Uz, 0, pf, tid);
    mma_half<false>(xs1, sm + W1, accZ, mrow0, ncol0, g, t);
    sts_w(sm + W0, pf, tid); __syncthreads();
    // H2: h@Uz (half 0)
    ldg_tr(Uz, 1, pf, tid);
    mma_half<true>(hs0, sm + W0, accZ, mrow0, ncol0, g, t);
    sts_w(sm + W1, pf, tid); __syncthreads();
    // H3: h@Uz (half 1)
    ldg_trsum(Wr, Ur, 0, pf, tid);
    mma_half<true>(hs1, sm + W1, accZ, mrow0, ncol0, g, t);
    sts_w(sm + W0, pf, tid); __syncthreads();
    // H4: x@(Wr+Ur) (half 0)
    ldg_trsum(Wr, Ur, 1, pf, tid);
    ZERO_ACC(acc);
    mma_half<false>(xs0, sm + W0, acc, mrow0, ncol0, g, t);
    sts_w(sm + W1, pf, tid); __syncthreads();
    // H5: x@(Wr+Ur) (half 1)
    ldg_nat(Wh, 0, pf, tid);
    mma_half<false>(xs1, sm + W1, acc, mrow0, ncol0, g, t);
    sts_w(sm + W0, pf, tid);

    // ---- E1: z = sigmoid(accZ + bz) in place; rh = sigmoid(acc + br) * h -> HS ----
#pragma unroll
    for (int nc = 0; nc < 8; ++nc) {
        int c0 = ncol0 + nc * 8 + 2 * t;
        float bz0 = sm[SBIAS + c0], bz1 = sm[SBIAS + c0 + 1];
        accZ[nc][0] = sigmoidf_(accZ[nc][0] + bz0);
        accZ[nc][1] = sigmoidf_(accZ[nc][1] + bz1);
        accZ[nc][2] = sigmoidf_(accZ[nc][2] + bz0);
        accZ[nc][3] = sigmoidf_(accZ[nc][3] + bz1);

        float br0 = sm[SBIAS + D + c0], br1 = sm[SBIAS + D + c0 + 1];
        int rA = mrow0 + g, rB = rA + 8;
        float2 hA = *(float2*)(sm + HS + rA * LDA + c0);
        float2 hB = *(float2*)(sm + HS + rB * LDA + c0);
        float r0 = sigmoidf_(acc[nc][0] + br0);
        float r1 = sigmoidf_(acc[nc][1] + br1);
        float r2 = sigmoidf_(acc[nc][2] + br0);
        float r3 = sigmoidf_(acc[nc][3] + br1);
        *(float2*)(sm + HS + rA * LDA + c0) = make_float2(f2tf(r0 * hA.x), f2tf(r1 * hA.y));
        *(float2*)(sm + HS + rB * LDA + c0) = make_float2(f2tf(r2 * hB.x), f2tf(r3 * hB.y));
    }
    __syncthreads();

    // H6: x@Wh^T (half 0)
    ldg_nat(Wh, 1, pf, tid);
    ZERO_ACC(acc);
    mma_half<false>(xs0, sm + W0, acc, mrow0, ncol0, g, t);
    sts_w(sm + W1, pf, tid); __syncthreads();
    // H7: x@Wh^T (half 1)
    ldg_nat(Uh, 0, pf, tid);
    mma_half<false>(xs1, sm + W1, acc, mrow0, ncol0, g, t);
    sts_w(sm + W0, pf, tid); __syncthreads();
    // H8: rh@Uh^T (half 0) — HS holds rounded r*h
    ldg_nat(Uh, 1, pf, tid);
    mma_half<false>(hs0, sm + W0, acc, mrow0, ncol0, g, t);
    sts_w(sm + W1, pf, tid); __syncthreads();
    // H9: rh@Uh^T (half 1)
    mma_half<false>(hs1, sm + W1, acc, mrow0, ncol0, g, t);

    // ---- E2: h_cand = tanh(acc + bh); h_t = (1-z)h + z*h_cand ----
#pragma unroll
    for (int nc = 0; nc < 8; ++nc) {
        int c0 = ncol0 + nc * 8 + 2 * t;
        float bh0 = sm[SBIAS + 2 * D + c0], bh1 = sm[SBIAS + 2 * D + c0 + 1];
        long long rA = row0 + mrow0 + g, rB = rA + 8;
        float2 hA = *(const float2*)(h + rA * D + c0);   // exact h (gmem re-read)
        float2 hB = *(const float2*)(h + rB * D + c0);
        float hc0 = tanhf(acc[nc][0] + bh0);
        float hc1 = tanhf(acc[nc][1] + bh1);
        float hc2 = tanhf(acc[nc][2] + bh0);
        float hc3 = tanhf(acc[nc][3] + bh1);
        float ht0 = (1.f - accZ[nc][0]) * hA.x + accZ[nc][0] * hc0;
        float ht1 = (1.f - accZ[nc][1]) * hA.y + accZ[nc][1] * hc1;
        float ht2 = (1.f - accZ[nc][2]) * hB.x + accZ[nc][2] * hc2;
        float ht3 = (1.f - accZ[nc][3]) * hB.y + accZ[nc][3] * hc3;
        *(float2*)(out + rA * D + c0)            = make_float2(ht0, ht1);
        *(float2*)(out + rB * D + c0)            = make_float2(ht2, ht3);
        *(float2*)(out + half_off + rA * D + c0) = make_float2(hc0, hc1);
        *(float2*)(out + half_off + rB * D + c0) = make_float2(hc2, hc3);
    }
}

// ---------------------------------------------------------------------------
// launch
// ---------------------------------------------------------------------------
extern "C" void kernel_launch(void* const* d_in, const int* in_sizes, int n_in,
                              void* d_out, int out_size) {
    const float* x  = (const float*)d_in[0];
    const float* h  = (const float*)d_in[1];
    const float* Wz = (const float*)d_in[2];
    const float* Uz = (const float*)d_in[3];
    const float* Bz = (const float*)d_in[4];
    const float* Wr = (const float*)d_in[5];
    const float* Ur = (const float*)d_in[6];
    const float* Br = (const float*)d_in[7];
    const float* Wh = (const float*)d_in[8];
    const float* Uh = (const float*)d_in[9];
    const float* Bh = (const float*)d_in[10];

    const int rows = in_sizes[0] / D;      // 262144
    const int grid = rows / 128;           // 2048

    cudaFuncSetAttribute(gru_kernel, cudaFuncAttributeMaxDynamicSharedMemorySize, SMEM_BYTES);

    bias_kernel<<<1, D>>>(Bz, Br, Bh);

    long long half_off = (long long)out_size / 2;   // h_t first, h_cand second
    gru_kernel<<<grid, NT, SMEM_BYTES>>>(x, h, Wz, Uz, Wr, Ur, Wh, Uh,
                                         (float*)d_out, half_off);
}